// round 3
// baseline (speedup 1.0000x reference)
#include <cuda_runtime.h>
#include <cstdint>

#define N_NODES_MAX 100000
#define HIDDEN 64

// Scratch. INVARIANT: g_deg and g_accum are all-zero between kernel_launch
// calls (static zero-init establishes it; out_kernel restores it each call).
__device__ float g_deg[N_NODES_MAX];     // zero between calls
__device__ float g_accum[N_NODES_MAX];   // zero between calls
__device__ float g_uz[HIDDEN], g_cz[HIDDEN], g_uh[HIDDEN], g_ch[HIDDEN];

__device__ __forceinline__ float tanh_approx(float x) {
    float y;
    asm("tanh.approx.f32 %0, %1;" : "=f"(y) : "f"(x));
    return y;
}

// --- pass 1 over edges: degree accumulation (+ const fold in block 0) ---
__global__ void deg_kernel(const int* __restrict__ dst, const float* __restrict__ ew,
                           int E, int vec_ok,
                           const float* __restrict__ Wz, const float* __restrict__ bz,
                           const float* __restrict__ Lz, const float* __restrict__ lbz,
                           const float* __restrict__ Wh, const float* __restrict__ bh,
                           const float* __restrict__ Lh, const float* __restrict__ lbh) {
    // fold tiny matrices once: uz = Wz@Lz_top, cz = bz@Lz_top + lbz, same for h
    if (blockIdx.x == 0 && threadIdx.x < HIDDEN) {
        int j = threadIdx.x;
        float uz = 0.f, cz = lbz[j], uh = 0.f, ch = lbh[j];
        #pragma unroll 8
        for (int k = 0; k < HIDDEN; k++) {
            float lz = Lz[k * HIDDEN + j];
            float lh = Lh[k * HIDDEN + j];
            uz = fmaf(Wz[k], lz, uz);
            cz = fmaf(bz[k], lz, cz);
            uh = fmaf(Wh[k], lh, uh);
            ch = fmaf(bh[k], lh, ch);
        }
        g_uz[j] = uz; g_cz[j] = cz; g_uh[j] = uh; g_ch[j] = ch;
    }

    int tid = blockIdx.x * blockDim.x + threadIdx.x;
    if (vec_ok) {
        int nvec = E >> 2;
        if (tid < nvec) {
            int4   d4 = ((const int4*)dst)[tid];
            float4 w4 = ((const float4*)ew)[tid];
            atomicAdd(&g_deg[d4.x], w4.x);
            atomicAdd(&g_deg[d4.y], w4.y);
            atomicAdd(&g_deg[d4.z], w4.z);
            atomicAdd(&g_deg[d4.w], w4.w);
        }
        int e = (nvec << 2) + tid;
        if (e < E && tid < (E - (nvec << 2)))
            atomicAdd(&g_deg[dst[e]], ew[e]);
    } else {
        for (int e = tid; e < E; e += gridDim.x * blockDim.x)
            atomicAdd(&g_deg[dst[e]], ew[e]);
    }
}

// --- pass 2 over edges: normalized scatter-add; dinv computed inline ---
__global__ void agg_kernel(const int* __restrict__ src, const int* __restrict__ dst,
                           const float* __restrict__ ew, const float* __restrict__ x,
                           int E, int vec_ok) {
    int tid = blockIdx.x * blockDim.x + threadIdx.x;
    if (vec_ok) {
        int nvec = E >> 2;
        if (tid < nvec) {
            int4   s4 = ((const int4*)src)[tid];
            int4   d4 = ((const int4*)dst)[tid];
            float4 w4 = ((const float4*)ew)[tid];
            // px[s] = rsqrt(deg[s]+1) * x[s], computed on the fly (L2-resident gathers)
            float p0 = rsqrtf(__ldg(&g_deg[s4.x]) + 1.0f) * __ldg(&x[s4.x]);
            float p1 = rsqrtf(__ldg(&g_deg[s4.y]) + 1.0f) * __ldg(&x[s4.y]);
            float p2 = rsqrtf(__ldg(&g_deg[s4.z]) + 1.0f) * __ldg(&x[s4.z]);
            float p3 = rsqrtf(__ldg(&g_deg[s4.w]) + 1.0f) * __ldg(&x[s4.w]);
            atomicAdd(&g_accum[d4.x], w4.x * p0);
            atomicAdd(&g_accum[d4.y], w4.y * p1);
            atomicAdd(&g_accum[d4.z], w4.z * p2);
            atomicAdd(&g_accum[d4.w], w4.w * p3);
        }
        int e = (nvec << 2) + tid;
        if (e < E && tid < (E - (nvec << 2))) {
            int s = src[e];
            atomicAdd(&g_accum[dst[e]],
                      ew[e] * rsqrtf(__ldg(&g_deg[s]) + 1.0f) * __ldg(&x[s]));
        }
    } else {
        for (int e = tid; e < E; e += gridDim.x * blockDim.x) {
            int s = src[e];
            atomicAdd(&g_accum[dst[e]],
                      ew[e] * rsqrtf(__ldg(&g_deg[s]) + 1.0f) * __ldg(&x[s]));
        }
    }
}

// --- pointwise epilogue; resets g_deg and g_accum (zero invariant) ---
__global__ void out_kernel(const float* __restrict__ x, const float* __restrict__ Wout,
                           const float* __restrict__ bout, float* __restrict__ out, int n) {
    __shared__ float s_uz[HIDDEN], s_cz[HIDDEN], s_uh[HIDDEN], s_ch[HIDDEN], s_w[HIDDEN];
    for (int j = threadIdx.x; j < HIDDEN; j += blockDim.x) {
        s_uz[j] = g_uz[j]; s_cz[j] = g_cz[j];
        s_uh[j] = g_uh[j]; s_ch[j] = g_ch[j];
        s_w[j]  = Wout[j];
    }
    __syncthreads();
    int i = blockIdx.x * blockDim.x + threadIdx.x;
    if (i < n) {
        float d    = g_deg[i] + 1.0f;
        g_deg[i]   = 0.0f;              // restore invariant
        float acc0 = g_accum[i];
        g_accum[i] = 0.0f;              // restore invariant
        float di  = rsqrtf(d);
        float a   = di * (acc0 + di * x[i]);
        float acc = bout[0];
        #pragma unroll 8
        for (int j = 0; j < HIDDEN; j++) {
            // (1-z) = 0.5*(1 - tanh(zarg/2));  Hn = (1-Z)*Ht  (H0=0, R branch dead)
            float zarg = fmaf(a, s_uz[j], s_cz[j]);
            float tz = tanh_approx(0.5f * zarg);
            float th = tanh_approx(fmaf(a, s_uh[j], s_ch[j]));
            float h = fmaxf(0.5f * (1.0f - tz) * th, 0.0f);
            acc = fmaf(h, s_w[j], acc);
        }
        out[i] = acc;
    }
}

extern "C" void kernel_launch(void* const* d_in, const int* in_sizes, int n_in,
                              void* d_out, int out_size) {
    const float* x    = (const float*)d_in[0];
    const float* ew   = (const float*)d_in[1];
    const float* Wz   = (const float*)d_in[2];
    const float* bz   = (const float*)d_in[3];
    const float* Lz   = (const float*)d_in[4];
    const float* lbz  = (const float*)d_in[5];
    // d_in[6..9]: Wr, br, Lr, lbr -- dead (H0 = 0 makes H*R = 0)
    const float* Wh   = (const float*)d_in[10];
    const float* bh   = (const float*)d_in[11];
    const float* Lh   = (const float*)d_in[12];
    const float* lbh  = (const float*)d_in[13];
    const float* Wout = (const float*)d_in[14];
    const float* bout = (const float*)d_in[15];
    const int*   eidx = (const int*)d_in[16];

    int N = in_sizes[0];
    int E = in_sizes[1];
    const int* src = eidx;
    const int* dst = eidx + E;

    float* out = (float*)d_out;

    int vec_ok = (((uintptr_t)src & 15) == 0) && (((uintptr_t)dst & 15) == 0) &&
                 (((uintptr_t)ew  & 15) == 0);

    const int TBE = 256;
    int nb_e;
    if (vec_ok) {
        int nvec = E >> 2;
        nb_e = (nvec + TBE - 1) / TBE;
        if (nb_e < 1) nb_e = 1;
    } else {
        nb_e = (E + TBE - 1) / TBE;
    }

    const int TBO = 128;                 // finer wave granularity for the epilogue
    int nb_o = (N + TBO - 1) / TBO;

    deg_kernel<<<nb_e, TBE>>>(dst, ew, E, vec_ok, Wz, bz, Lz, lbz, Wh, bh, Lh, lbh);
    agg_kernel<<<nb_e, TBE>>>(src, dst, ew, x, E, vec_ok);
    out_kernel<<<nb_o, TBO>>>(x, Wout, bout, out, N);
}

// round 5
// speedup vs baseline: 1.5199x; 1.5199x over previous
#include <cuda_runtime.h>
#include <cstdint>

#define N_NODES_MAX 100000
#define HIDDEN 64
#define LUT_N 8192
#define LUT_MIN (-32.0f)
#define LUT_RANGE 64.0f

// Scratch. INVARIANT: g_deg and g_accum are all-zero between kernel_launch
// calls (static zero-init; dinv_kernel / out_kernel restore them each call).
__device__ float g_deg[N_NODES_MAX];     // zero between calls
__device__ float g_accum[N_NODES_MAX];   // zero between calls
__device__ float g_dinv[N_NODES_MAX];
__device__ float g_px[N_NODES_MAX];      // dinv[i]*x[i]
__device__ float g_lut[LUT_N + 2];       // g(a) lookup, linear interp

__device__ __forceinline__ float tanh_approx(float x) {
    float y;
    asm("tanh.approx.f32 %0, %1;" : "=f"(y) : "f"(x));
    return y;
}

// ---------------------------------------------------------------------------
// Pass 1 over edges: degree accumulation. Blocks < 32 additionally build the
// g(a) LUT (each re-folds the tiny matrices independently -> no cross-block
// ordering needed).
// ---------------------------------------------------------------------------
__global__ void deg_kernel(const int* __restrict__ dst, const float* __restrict__ ew,
                           int E, int vec_ok,
                           const float* __restrict__ Wz, const float* __restrict__ bz,
                           const float* __restrict__ Lz, const float* __restrict__ lbz,
                           const float* __restrict__ Wh, const float* __restrict__ bh,
                           const float* __restrict__ Lh, const float* __restrict__ lbh,
                           const float* __restrict__ Wout, const float* __restrict__ bout) {
    // --- LUT build (blocks 0..31) ---
    int lutBlocks = gridDim.x < 32 ? gridDim.x : 32;
    __shared__ float s_uz[HIDDEN], s_cz[HIDDEN], s_uh[HIDDEN], s_ch[HIDDEN], s_w[HIDDEN];
    __shared__ float s_b0;
    if (blockIdx.x < lutBlocks) {
        int j = threadIdx.x;
        if (j < HIDDEN) {
            float uz = 0.f, cz = lbz[j], uh = 0.f, ch = lbh[j];
            #pragma unroll 8
            for (int k = 0; k < HIDDEN; k++) {
                float lz = Lz[k * HIDDEN + j];
                float lh = Lh[k * HIDDEN + j];
                uz = fmaf(Wz[k], lz, uz);
                cz = fmaf(bz[k], lz, cz);
                uh = fmaf(Wh[k], lh, uh);
                ch = fmaf(bh[k], lh, ch);
            }
            s_uz[j] = uz; s_cz[j] = cz; s_uh[j] = uh; s_ch[j] = ch;
            s_w[j] = Wout[j];
        }
        if (j == 0) s_b0 = bout[0];
        __syncthreads();
        const float step = LUT_RANGE / (float)LUT_N;
        for (int entry = blockIdx.x * blockDim.x + threadIdx.x;
             entry <= LUT_N + 1; entry += lutBlocks * blockDim.x) {
            float a = LUT_MIN + (float)entry * step;
            float acc = s_b0;
            #pragma unroll 8
            for (int jj = 0; jj < HIDDEN; jj++) {
                float tz = tanh_approx(0.5f * fmaf(a, s_uz[jj], s_cz[jj]));
                float th = tanh_approx(fmaf(a, s_uh[jj], s_ch[jj]));
                float h = fmaxf(0.5f * (1.0f - tz) * th, 0.0f);
                acc = fmaf(h, s_w[jj], acc);
            }
            g_lut[entry] = acc;
        }
    }

    // --- edge work: 4 quads per thread, loads front-batched (MLP_p1 = 8) ---
    int tid = blockIdx.x * blockDim.x + threadIdx.x;
    int NT  = gridDim.x * blockDim.x;
    if (vec_ok) {
        int nvec = E >> 2;
        int4 d4[4]; float4 w4[4]; bool v[4];
        #pragma unroll
        for (int k = 0; k < 4; k++) {
            int i = tid + k * NT;
            v[k] = (i < nvec);
            if (v[k]) { d4[k] = ((const int4*)dst)[i]; w4[k] = ((const float4*)ew)[i]; }
        }
        #pragma unroll
        for (int k = 0; k < 4; k++) {
            if (v[k]) {
                atomicAdd(&g_deg[d4[k].x], w4[k].x);
                atomicAdd(&g_deg[d4[k].y], w4[k].y);
                atomicAdd(&g_deg[d4[k].z], w4[k].z);
                atomicAdd(&g_deg[d4[k].w], w4[k].w);
            }
        }
        int tail = E - (nvec << 2);
        if (tid < tail) {
            int e = (nvec << 2) + tid;
            atomicAdd(&g_deg[dst[e]], ew[e]);
        }
    } else {
        for (int e = tid; e < E; e += NT)
            atomicAdd(&g_deg[dst[e]], ew[e]);
    }
}

// ---------------------------------------------------------------------------
// dinv + px precompute; resets g_deg (zero invariant). Vectorized.
// ---------------------------------------------------------------------------
__global__ void dinv_kernel(const float* __restrict__ x, int n) {
    int i = blockIdx.x * blockDim.x + threadIdx.x;
    int nvec = n >> 2;
    if (i < nvec) {
        float4 d4 = ((const float4*)g_deg)[i];
        float4 x4 = ((const float4*)x)[i];
        float4 di, px;
        di.x = rsqrtf(d4.x + 1.0f); px.x = di.x * x4.x;
        di.y = rsqrtf(d4.y + 1.0f); px.y = di.y * x4.y;
        di.z = rsqrtf(d4.z + 1.0f); px.z = di.z * x4.z;
        di.w = rsqrtf(d4.w + 1.0f); px.w = di.w * x4.w;
        ((float4*)g_dinv)[i] = di;
        ((float4*)g_px)[i]   = px;
        ((float4*)g_deg)[i]  = make_float4(0.f, 0.f, 0.f, 0.f);
    }
    int tail = n - (nvec << 2);
    if (i < tail) {
        int j = (nvec << 2) + i;
        float di = rsqrtf(g_deg[j] + 1.0f);
        g_dinv[j] = di;
        g_px[j]   = di * x[j];
        g_deg[j]  = 0.0f;
    }
}

// ---------------------------------------------------------------------------
// Pass 2 over edges: normalized scatter-add. 4 quads/thread, front-batched.
// ---------------------------------------------------------------------------
__global__ void agg_kernel(const int* __restrict__ src, const int* __restrict__ dst,
                           const float* __restrict__ ew, int E, int vec_ok) {
    int tid = blockIdx.x * blockDim.x + threadIdx.x;
    int NT  = gridDim.x * blockDim.x;
    if (vec_ok) {
        int nvec = E >> 2;
        int4 s4[4], d4[4]; float4 w4[4]; bool v[4];
        #pragma unroll
        for (int k = 0; k < 4; k++) {
            int i = tid + k * NT;
            v[k] = (i < nvec);
            if (v[k]) {
                s4[k] = ((const int4*)src)[i];
                d4[k] = ((const int4*)dst)[i];
                w4[k] = ((const float4*)ew)[i];
            }
        }
        // gathers (L2-resident px), batched
        float p[4][4];
        #pragma unroll
        for (int k = 0; k < 4; k++) {
            if (v[k]) {
                p[k][0] = __ldg(&g_px[s4[k].x]);
                p[k][1] = __ldg(&g_px[s4[k].y]);
                p[k][2] = __ldg(&g_px[s4[k].z]);
                p[k][3] = __ldg(&g_px[s4[k].w]);
            }
        }
        #pragma unroll
        for (int k = 0; k < 4; k++) {
            if (v[k]) {
                atomicAdd(&g_accum[d4[k].x], w4[k].x * p[k][0]);
                atomicAdd(&g_accum[d4[k].y], w4[k].y * p[k][1]);
                atomicAdd(&g_accum[d4[k].z], w4[k].z * p[k][2]);
                atomicAdd(&g_accum[d4[k].w], w4[k].w * p[k][3]);
            }
        }
        int tail = E - (nvec << 2);
        if (tid < tail) {
            int e = (nvec << 2) + tid;
            atomicAdd(&g_accum[dst[e]], ew[e] * __ldg(&g_px[src[e]]));
        }
    } else {
        for (int e = tid; e < E; e += NT)
            atomicAdd(&g_accum[dst[e]], ew[e] * __ldg(&g_px[src[e]]));
    }
}

// ---------------------------------------------------------------------------
// Epilogue via LUT; resets g_accum (zero invariant). Vectorized.
// ---------------------------------------------------------------------------
__global__ void out_kernel(const float* __restrict__ x, float* __restrict__ out, int n) {
    const float inv_step = (float)LUT_N / LUT_RANGE;
    int i = blockIdx.x * blockDim.x + threadIdx.x;
    int nvec = n >> 2;
    if (i < nvec) {
        float4 di4 = ((const float4*)g_dinv)[i];
        float4 ac4 = ((const float4*)g_accum)[i];
        float4 x4  = ((const float4*)x)[i];
        ((float4*)g_accum)[i] = make_float4(0.f, 0.f, 0.f, 0.f);
        float a[4], r[4];
        a[0] = di4.x * (ac4.x + di4.x * x4.x);
        a[1] = di4.y * (ac4.y + di4.y * x4.y);
        a[2] = di4.z * (ac4.z + di4.z * x4.z);
        a[3] = di4.w * (ac4.w + di4.w * x4.w);
        #pragma unroll
        for (int k = 0; k < 4; k++) {
            float t = (a[k] - LUT_MIN) * inv_step;
            t = fminf(fmaxf(t, 0.0f), (float)LUT_N);
            int   idx  = (int)t;
            float frac = t - (float)idx;
            float lo = g_lut[idx];
            float hi = g_lut[idx + 1];
            r[k] = fmaf(hi - lo, frac, lo);
        }
        ((float4*)out)[i] = make_float4(r[0], r[1], r[2], r[3]);
    }
    int tail = n - (nvec << 2);
    if (i < tail) {
        int j = (nvec << 2) + i;
        float di = g_dinv[j];
        float a  = di * (g_accum[j] + di * x[j]);
        g_accum[j] = 0.0f;
        float t = (a - LUT_MIN) * inv_step;
        t = fminf(fmaxf(t, 0.0f), (float)LUT_N);
        int   idx  = (int)t;
        float frac = t - (float)idx;
        float lo = g_lut[idx];
        float hi = g_lut[idx + 1];
        out[j] = fmaf(hi - lo, frac, lo);
    }
}

extern "C" void kernel_launch(void* const* d_in, const int* in_sizes, int n_in,
                              void* d_out, int out_size) {
    const float* x    = (const float*)d_in[0];
    const float* ew   = (const float*)d_in[1];
    const float* Wz   = (const float*)d_in[2];
    const float* bz   = (const float*)d_in[3];
    const float* Lz   = (const float*)d_in[4];
    const float* lbz  = (const float*)d_in[5];
    // d_in[6..9]: Wr, br, Lr, lbr -- dead (H0 = 0 makes H*R = 0)
    const float* Wh   = (const float*)d_in[10];
    const float* bh   = (const float*)d_in[11];
    const float* Lh   = (const float*)d_in[12];
    const float* lbh  = (const float*)d_in[13];
    const float* Wout = (const float*)d_in[14];
    const float* bout = (const float*)d_in[15];
    const int*   eidx = (const int*)d_in[16];

    int N = in_sizes[0];
    int E = in_sizes[1];
    const int* src = eidx;
    const int* dst = eidx + E;
    float* out = (float*)d_out;

    int vec_ok = (((uintptr_t)src & 15) == 0) && (((uintptr_t)dst & 15) == 0) &&
                 (((uintptr_t)ew  & 15) == 0) && (((uintptr_t)x & 15) == 0) &&
                 (((uintptr_t)out & 15) == 0);

    const int TB = 256;
    int nb_e;
    if (vec_ok) {
        int nvec = E >> 2;
        int nthreads = (nvec + 3) / 4;            // 4 quads per thread
        nb_e = (nthreads + TB - 1) / TB;
        if (nb_e < 1) nb_e = 1;
    } else {
        nb_e = 592;                               // grid-stride scalar fallback
    }

    int nb_n;
    if (vec_ok) {
        int nvec_n = N >> 2;
        nb_n = (nvec_n + TB - 1) / TB;
        if (nb_n < 1) nb_n = 1;
    } else {
        // scalar kernels still use the vec layout guards (n>>2 == coverage);
        // x/out are fp32 harness buffers -- they are 256B-aligned in practice,
        // but keep a safe dense grid if not.
        nb_n = (N + TB - 1) / TB;
    }

    deg_kernel<<<nb_e, TB>>>(dst, ew, E, vec_ok, Wz, bz, Lz, lbz,
                             Wh, bh, Lh, lbh, Wout, bout);
    dinv_kernel<<<nb_n, TB>>>(x, N);
    agg_kernel<<<nb_e, TB>>>(src, dst, ew, E, vec_ok);
    out_kernel<<<nb_n, TB>>>(x, out, N);
}